// round 2
// baseline (speedup 1.0000x reference)
#include <cuda_runtime.h>

#define HH 1024
#define WW 1024
#define HW (HH*WW)
#define NT 256
#define NBF (HW/NT)
#define NB2 592

// ---------------- device scratch ----------------
__device__ float g_rhoc[HW];
__device__ float g_gi0[HW];
__device__ float g_gi1[HW];
__device__ float g_u[2][2*HW];    // ping-pong u buffers, [comp][HW] inside
__device__ float g_p[2][4*HW];    // ping-pong p buffers, [k][HW] inside, k=i*2+j
__device__ float g_partial[NB2];
__device__ unsigned int g_count;
__device__ float g_S;

// ---------------- K0: rho_c, grad_im; zero P_0 ----------------
__global__ void k_init(const float* __restrict__ x, const float* __restrict__ gw) {
    int idx = blockIdx.x * NT + threadIdx.x;
    int y = idx >> 10, xx = idx & (WW - 1);
    const float* __restrict__ x1 = x + HW;

    g_rhoc[idx] = x1[idx] - x[idx];

    float a = 0.f, b = 0.f;
    #pragma unroll
    for (int dy = -1; dy <= 1; dy++)
        #pragma unroll
        for (int dx = -1; dx <= 1; dx++) {
            int yy = y + dy, xc = xx + dx;
            float v = (yy >= 0 && yy < HH && xc >= 0 && xc < WW) ? x1[yy * WW + xc] : 0.f;
            int k = (dy + 1) * 3 + (dx + 1);
            a += v * __ldg(&gw[k]);
            b += v * __ldg(&gw[9 + k]);
        }
    g_gi0[idx] = a;
    g_gi1[idx] = b;

    g_p[0][idx] = 0.f; g_p[0][HW + idx] = 0.f;
    g_p[0][2*HW + idx] = 0.f; g_p[0][3*HW + idx] = 0.f;
    if (idx == 0) g_count = 0u;
}

// ---------------- K_R: S_t = sum |sobel(u_t)| (deterministic) ----------------
__global__ void k_reduce(const float* __restrict__ u, const float* __restrict__ gw) {
    float w0[9], w1[9];
    #pragma unroll
    for (int i = 0; i < 9; i++) { w0[i] = __ldg(&gw[i]); w1[i] = __ldg(&gw[9 + i]); }
    const float* __restrict__ u1 = u + HW;

    float acc = 0.f;
    int stride = gridDim.x * NT;
    for (int idx = blockIdx.x * NT + threadIdx.x; idx < HW; idx += stride) {
        int y = idx >> 10, xx = idx & (WW - 1);
        float s00 = 0.f, s01 = 0.f, s10 = 0.f, s11 = 0.f;
        #pragma unroll
        for (int dy = -1; dy <= 1; dy++)
            #pragma unroll
            for (int dx = -1; dx <= 1; dx++) {
                int yy = y + dy, xc = xx + dx;
                bool in = (yy >= 0 && yy < HH && xc >= 0 && xc < WW);
                int o = yy * WW + xc;
                float va = in ? u[o]  : 0.f;
                float vb = in ? u1[o] : 0.f;
                int k = (dy + 1) * 3 + (dx + 1);
                s00 += va * w0[k]; s01 += va * w1[k];
                s10 += vb * w0[k]; s11 += vb * w1[k];
            }
        acc += fabsf(s00) + fabsf(s01) + fabsf(s10) + fabsf(s11);
    }

    __shared__ float sm[NT];
    int tid = threadIdx.x;
    sm[tid] = acc;
    __syncthreads();
    for (int s = NT / 2; s > 0; s >>= 1) {
        if (tid < s) sm[tid] += sm[tid + s];
        __syncthreads();
    }
    __shared__ bool isLast;
    if (tid == 0) {
        g_partial[blockIdx.x] = sm[0];
        __threadfence();
        unsigned prev = atomicAdd(&g_count, 1u);
        isLast = (prev == gridDim.x - 1);
    }
    __syncthreads();
    if (isLast && tid < 32) {
        float s = 0.f;
        for (int i = tid; i < (int)gridDim.x; i += 32) s += g_partial[i];
        #pragma unroll
        for (int o = 16; o > 0; o >>= 1) s += __shfl_down_sync(0xffffffffu, s, o);
        if (tid == 0) { g_S = s; g_count = 0u; }
    }
}

// ---------------- K_F: fused (recompute p_t at own/left/up) + u update ----------------
// MODE 0: t==0 (u=0, p=0, no p write). MODE 1: mid. MODE 2: last (no p write).
template<int MODE>
__global__ void k_fused(const float* __restrict__ uin, float* __restrict__ uout,
                        const float* __restrict__ pin, float* __restrict__ pout,
                        const float* __restrict__ gw,
                        const float* __restrict__ wx, const float* __restrict__ wy,
                        const float* __restrict__ lam, const float* __restrict__ tau,
                        const float* __restrict__ th) {
    int idx = blockIdx.x * NT + threadIdx.x;
    int y = idx >> 10, xx = idx & (WW - 1);

    float theta = __ldg(th);
    float tl = theta * __ldg(lam);

    float gi0 = g_gi0[idx], gi1 = g_gi1[idx];
    float nrm = gi0 * gi0 + gi1 * gi1;

    float w0[9], w1[9];
    float t0[3][4], t1[4][3];
    float u0c = 0.f, u1c = 0.f;
    if (MODE != 0) {
        #pragma unroll
        for (int i = 0; i < 9; i++) { w0[i] = __ldg(&gw[i]); w1[i] = __ldg(&gw[9 + i]); }
        const float* __restrict__ uin1 = uin + HW;
        // u0 tile: rows y-1..y+1, cols xx-2..xx+1
        #pragma unroll
        for (int r = 0; r < 3; r++) {
            int yy = y - 1 + r; bool vy = (yy >= 0 && yy < HH);
            #pragma unroll
            for (int c = 0; c < 4; c++) {
                int xc = xx - 2 + c;
                t0[r][c] = (vy && xc >= 0 && xc < WW) ? uin[yy * WW + xc] : 0.f;
            }
        }
        // u1 tile: rows y-2..y+1, cols xx-1..xx+1
        #pragma unroll
        for (int r = 0; r < 4; r++) {
            int yy = y - 2 + r; bool vy = (yy >= 0 && yy < HH);
            #pragma unroll
            for (int c = 0; c < 3; c++) {
                int xc = xx - 1 + c;
                t1[r][c] = (vy && xc >= 0 && xc < WW) ? uin1[yy * WW + xc] : 0.f;
            }
        }
        u0c = t0[1][2]; u1c = t1[2][1];
    }

    float rho = g_rhoc[idx] + gi0 * u0c + gi1 * u1c;
    float a = fabsf(rho);
    float thv = tl * nrm;
    float v0 = u0c, v1 = u1c;
    if (a < thv) {                 // thv > a >= 0 implies nrm > 0
        float q = rho / nrm;
        v0 -= q * gi0; v1 -= q * gi1;
    } else if (a > thv) {
        float s = (rho > 0.f) ? 1.f : ((rho < 0.f) ? -1.f : 0.f);
        float c = tl * s;
        v0 -= c * gi0; v1 -= c * gi1;
    }

    if (MODE == 0) {               // p_0 = 0 -> div = 0
        uout[idx] = v0; uout[HW + idx] = v1;
        return;
    }

    float rr = __ldg(tau) / theta;
    float inv = 1.f / (1.f + rr * g_S);

    // sobels: own(u0), left(u0), own(u1), up(u1), both filters each
    float G00 = 0.f, G01 = 0.f, L00 = 0.f, L01 = 0.f;
    float G10 = 0.f, G11 = 0.f, U10 = 0.f, U11 = 0.f;
    #pragma unroll
    for (int r = 0; r < 3; r++)
        #pragma unroll
        for (int c = 0; c < 3; c++) {
            float wa = w0[r * 3 + c], wb = w1[r * 3 + c];
            G00 += t0[r][c + 1] * wa;  G01 += t0[r][c + 1] * wb;
            L00 += t0[r][c]     * wa;  L01 += t0[r][c]     * wb;
            G10 += t1[r + 1][c] * wa;  G11 += t1[r + 1][c] * wb;
            U10 += t1[r][c]     * wa;  U11 += t1[r][c]     * wb;
        }

    // p_t = (p_{t-1} + r*G) * inv at the 3 needed positions
    float p00 = (pin[idx]          + rr * G00) * inv;
    float p01 = (pin[HW + idx]     + rr * G01) * inv;
    float p10 = (pin[2*HW + idx]   + rr * G10) * inv;
    float p11 = (pin[3*HW + idx]   + rr * G11) * inv;
    float p00l = 0.f, p01l = 0.f;
    if (xx > 0) {
        p00l = (pin[idx - 1]      + rr * L00) * inv;
        p01l = (pin[HW + idx - 1] + rr * L01) * inv;
    }
    float p10u = 0.f, p11u = 0.f;
    if (y > 0) {
        p10u = (pin[2*HW + idx - WW] + rr * U10) * inv;
        p11u = (pin[3*HW + idx - WW] + rr * U11) * inv;
    }

    float wx0 = __ldg(&wx[0]), wx1v = __ldg(&wx[1]);
    float wy0 = __ldg(&wy[0]), wy1v = __ldg(&wy[1]);
    float d0 = p00l * wx0 + p00 * wx1v + p10u * wy0 + p10 * wy1v;
    float d1 = p01l * wx0 + p01 * wx1v + p11u * wy0 + p11 * wy1v;

    uout[idx]      = v0 + theta * d0;
    uout[HW + idx] = v1 + theta * d1;

    if (MODE == 1) {
        pout[idx]          = p00;
        pout[HW + idx]     = p01;
        pout[2*HW + idx]   = p10;
        pout[3*HW + idx]   = p11;
    }
}

// ---------------- launch ----------------
extern "C" void kernel_launch(void* const* d_in, const int* in_sizes, int n_in,
                              void* d_out, int out_size) {
    const float* x   = (const float*)d_in[0];
    const float* gw  = (const float*)d_in[1];
    const float* wx  = (const float*)d_in[2];
    const float* wy  = (const float*)d_in[3];
    const float* lam = (const float*)d_in[4];
    const float* tau = (const float*)d_in[5];
    const float* th  = (const float*)d_in[6];
    float* out = (float*)d_out;

    float* ubase; cudaGetSymbolAddress((void**)&ubase, g_u);
    float* pbase; cudaGetSymbolAddress((void**)&pbase, g_p);
    float* ubuf[2] = { ubase, ubase + 2*HW };
    float* pbuf[2] = { pbase, pbase + 4*HW };

    k_init<<<NBF, NT>>>(x, gw);

    // t = 0: u_1 = v(u_0=0); p_0 = 0 stays in pbuf[0]
    k_fused<0><<<NBF, NT>>>(nullptr, ubuf[1], nullptr, nullptr, gw, wx, wy, lam, tau, th);

    for (int t = 1; t <= 9; t++) {
        // u_t lives in ubuf[t&1]; P_{t-1} in pbuf[(t+1)&1]; P_t -> pbuf[t&1]
        k_reduce<<<NB2, NT>>>(ubuf[t & 1], gw);
        float* uo = (t == 9) ? out : ubuf[(t + 1) & 1];
        if (t < 9)
            k_fused<1><<<NBF, NT>>>(ubuf[t & 1], uo, pbuf[(t + 1) & 1], pbuf[t & 1],
                                    gw, wx, wy, lam, tau, th);
        else
            k_fused<2><<<NBF, NT>>>(ubuf[t & 1], uo, pbuf[(t + 1) & 1], nullptr,
                                    gw, wx, wy, lam, tau, th);
    }
}

// round 3
// speedup vs baseline: 1.3697x; 1.3697x over previous
#include <cuda_runtime.h>

#define HH 1024
#define WW 1024
#define HW (HH*WW)
#define NT 256
#define NB4 (HW/4/NT)   // 1024 blocks, 4 px/thread

// ---------------- device scratch (16B aligned for float4) ----------------
__device__ __align__(16) float g_rhoc[HW];
__device__ __align__(16) float g_gi0[HW];
__device__ __align__(16) float g_gi1[HW];
__device__ __align__(16) float g_u[2][2*HW];
__device__ __align__(16) float g_p[2][4*HW];
__device__ float g_partial[NB4];
__device__ unsigned int g_count;
__device__ float g_S;

__device__ __forceinline__ float4 ldg4(const float* p) { return *(const float4*)p; }
__device__ __forceinline__ float2 ldg2(const float* p) { return *(const float2*)p; }

// ---------------- K0: rho_c, grad_im; zero P_0 (vectorized) ----------------
__global__ void k_init(const float* __restrict__ x, const float* __restrict__ gw) {
    int t4 = blockIdx.x * NT + threadIdx.x;
    int pix = t4 * 4;
    int y = pix >> 10, x0 = pix & (WW - 1);
    const float* __restrict__ x1 = x + HW;

    float w0[9], w1[9];
    #pragma unroll
    for (int i = 0; i < 9; i++) { w0[i] = __ldg(&gw[i]); w1[i] = __ldg(&gw[9 + i]); }

    // tile rows y-1..y+1, cols x0-1..x0+4
    float t[3][6];
    #pragma unroll
    for (int r = 0; r < 3; r++) {
        int yy = y - 1 + r; bool vy = (yy >= 0 && yy < HH);
        const float* row = x1 + yy * WW;
        float l = (vy && x0 > 0) ? row[x0 - 1] : 0.f;
        float4 b = vy ? ldg4(row + x0) : make_float4(0.f,0.f,0.f,0.f);
        float rg = (vy && x0 < WW - 4) ? row[x0 + 4] : 0.f;
        t[r][0]=l; t[r][1]=b.x; t[r][2]=b.y; t[r][3]=b.z; t[r][4]=b.w; t[r][5]=rg;
    }

    float4 xc0 = ldg4(x + pix);
    float4 xc1 = ldg4(x1 + pix);
    float4 rc = make_float4(xc1.x-xc0.x, xc1.y-xc0.y, xc1.z-xc0.z, xc1.w-xc0.w);
    *(float4*)(g_rhoc + pix) = rc;

    float4 A, B;
    float* Ap = &A.x; float* Bp = &B.x;
    #pragma unroll
    for (int i = 0; i < 4; i++) {
        float a = 0.f, b = 0.f;
        #pragma unroll
        for (int r = 0; r < 3; r++)
            #pragma unroll
            for (int c = 0; c < 3; c++) {
                float v = t[r][i + c];
                a += v * w0[r*3+c]; b += v * w1[r*3+c];
            }
        Ap[i] = a; Bp[i] = b;
    }
    *(float4*)(g_gi0 + pix) = A;
    *(float4*)(g_gi1 + pix) = B;

    float4 z = make_float4(0.f,0.f,0.f,0.f);
    *(float4*)(g_p[0] + pix) = z;
    *(float4*)(g_p[0] + HW + pix) = z;
    *(float4*)(g_p[0] + 2*HW + pix) = z;
    *(float4*)(g_p[0] + 3*HW + pix) = z;
    if (pix == 0) g_count = 0u;
}

// ---------------- K_R: S = sum |sobel(u)| (vectorized, deterministic) ----------------
__global__ void k_reduce(const float* __restrict__ u, const float* __restrict__ gw) {
    float w0[9], w1[9];
    #pragma unroll
    for (int i = 0; i < 9; i++) { w0[i] = __ldg(&gw[i]); w1[i] = __ldg(&gw[9 + i]); }

    int t4 = blockIdx.x * NT + threadIdx.x;
    int pix = t4 * 4;
    int y = pix >> 10, x0 = pix & (WW - 1);

    float acc = 0.f;
    #pragma unroll
    for (int comp = 0; comp < 2; comp++) {
        const float* __restrict__ up = u + comp * HW;
        float t[3][6];
        #pragma unroll
        for (int r = 0; r < 3; r++) {
            int yy = y - 1 + r; bool vy = (yy >= 0 && yy < HH);
            const float* row = up + yy * WW;
            float l = (vy && x0 > 0) ? row[x0 - 1] : 0.f;
            float4 b = vy ? ldg4(row + x0) : make_float4(0.f,0.f,0.f,0.f);
            float rg = (vy && x0 < WW - 4) ? row[x0 + 4] : 0.f;
            t[r][0]=l; t[r][1]=b.x; t[r][2]=b.y; t[r][3]=b.z; t[r][4]=b.w; t[r][5]=rg;
        }
        #pragma unroll
        for (int i = 0; i < 4; i++) {
            float a = 0.f, b = 0.f;
            #pragma unroll
            for (int r = 0; r < 3; r++)
                #pragma unroll
                for (int c = 0; c < 3; c++) {
                    float v = t[r][i + c];
                    a += v * w0[r*3+c]; b += v * w1[r*3+c];
                }
            acc += fabsf(a) + fabsf(b);
        }
    }

    __shared__ float sm[NT];
    int tid = threadIdx.x;
    sm[tid] = acc;
    __syncthreads();
    for (int s = NT / 2; s > 0; s >>= 1) {
        if (tid < s) sm[tid] += sm[tid + s];
        __syncthreads();
    }
    __shared__ bool isLast;
    if (tid == 0) {
        g_partial[blockIdx.x] = sm[0];
        __threadfence();
        unsigned prev = atomicAdd(&g_count, 1u);
        isLast = (prev == gridDim.x - 1);
    }
    __syncthreads();
    if (isLast && tid < 32) {
        float s = 0.f;
        for (int i = tid; i < (int)gridDim.x; i += 32) s += g_partial[i];
        #pragma unroll
        for (int o = 16; o > 0; o >>= 1) s += __shfl_down_sync(0xffffffffu, s, o);
        if (tid == 0) { g_S = s; g_count = 0u; }
    }
}

// ---------------- K_F: fused p-recompute + u update, 4 px/thread ----------------
// MODE 0: t==0 (u=0,p=0). MODE 1: mid (writes p). MODE 2: last (no p write).
template<int MODE>
__global__ void k_fused(const float* __restrict__ uin, float* __restrict__ uout,
                        const float* __restrict__ pin, float* __restrict__ pout,
                        const float* __restrict__ gw,
                        const float* __restrict__ wx, const float* __restrict__ wy,
                        const float* __restrict__ lam, const float* __restrict__ tau,
                        const float* __restrict__ th) {
    int t4 = blockIdx.x * NT + threadIdx.x;
    int pix = t4 * 4;
    int y = pix >> 10, x0 = pix & (WW - 1);

    float theta = __ldg(th);
    float tl = theta * __ldg(lam);

    float4 GI0 = ldg4(g_gi0 + pix);
    float4 GI1 = ldg4(g_gi1 + pix);
    float4 RC  = ldg4(g_rhoc + pix);
    const float* gi0 = &GI0.x; const float* gi1 = &GI1.x; const float* rc = &RC.x;

    float w0[9], w1[9];
    float t0[3][8];   // u0: rows y-1..y+1, cols x0-2..x0+5
    float t1[4][6];   // u1: rows y-2..y+1, cols x0-1..x0+4
    if (MODE != 0) {
        #pragma unroll
        for (int i = 0; i < 9; i++) { w0[i] = __ldg(&gw[i]); w1[i] = __ldg(&gw[9 + i]); }
        const float* __restrict__ uin1 = uin + HW;
        #pragma unroll
        for (int r = 0; r < 3; r++) {
            int yy = y - 1 + r; bool vy = (yy >= 0 && yy < HH);
            const float* row = uin + yy * WW;
            float2 a = (vy && x0 > 0) ? ldg2(row + x0 - 2) : make_float2(0.f,0.f);
            float4 b = vy ? ldg4(row + x0) : make_float4(0.f,0.f,0.f,0.f);
            float2 c = (vy && x0 < WW - 4) ? ldg2(row + x0 + 4) : make_float2(0.f,0.f);
            t0[r][0]=a.x; t0[r][1]=a.y; t0[r][2]=b.x; t0[r][3]=b.y;
            t0[r][4]=b.z; t0[r][5]=b.w; t0[r][6]=c.x; t0[r][7]=c.y;
        }
        #pragma unroll
        for (int r = 0; r < 4; r++) {
            int yy = y - 2 + r; bool vy = (yy >= 0 && yy < HH);
            const float* row = uin1 + yy * WW;
            float l = (vy && x0 > 0) ? row[x0 - 1] : 0.f;
            float4 b = vy ? ldg4(row + x0) : make_float4(0.f,0.f,0.f,0.f);
            float rg = (vy && x0 < WW - 4) ? row[x0 + 4] : 0.f;
            t1[r][0]=l; t1[r][1]=b.x; t1[r][2]=b.y; t1[r][3]=b.z; t1[r][4]=b.w; t1[r][5]=rg;
        }
    }

    // pointwise v update for 4 pixels
    float v0[4], v1[4];
    #pragma unroll
    for (int i = 0; i < 4; i++) {
        float u0c = (MODE != 0) ? t0[1][2 + i] : 0.f;
        float u1c = (MODE != 0) ? t1[2][1 + i] : 0.f;
        float nrm = gi0[i]*gi0[i] + gi1[i]*gi1[i];
        float rho = rc[i] + gi0[i]*u0c + gi1[i]*u1c;
        float a = fabsf(rho);
        float thv = tl * nrm;
        float a0 = u0c, a1 = u1c;
        if (a < thv) {
            float q = rho / nrm;
            a0 -= q * gi0[i]; a1 -= q * gi1[i];
        } else if (a > thv) {
            float s = (rho > 0.f) ? 1.f : ((rho < 0.f) ? -1.f : 0.f);
            float c = tl * s;
            a0 -= c * gi0[i]; a1 -= c * gi1[i];
        }
        v0[i] = a0; v1[i] = a1;
    }

    if (MODE == 0) {
        *(float4*)(uout + pix)      = make_float4(v0[0],v0[1],v0[2],v0[3]);
        *(float4*)(uout + HW + pix) = make_float4(v1[0],v1[1],v1[2],v1[3]);
        return;
    }

    float rr = __ldg(tau) / theta;
    float inv = 1.f / (1.f + rr * g_S);

    // sobels for 4 own pixels + left-extra (u0) + up row (u1)
    float G00[4], G01[4], G10[4], G11[4], U10[4], U11[4];
    float L00 = 0.f, L01 = 0.f;
    #pragma unroll
    for (int i = 0; i < 4; i++) {
        float s00=0.f,s01=0.f,s10=0.f,s11=0.f,q10=0.f,q11=0.f;
        #pragma unroll
        for (int r = 0; r < 3; r++)
            #pragma unroll
            for (int c = 0; c < 3; c++) {
                float wa = w0[r*3+c], wb = w1[r*3+c];
                float va = t0[r][i + 1 + c];
                s00 += va * wa; s01 += va * wb;
                float vb = t1[r + 1][i + c];
                s10 += vb * wa; s11 += vb * wb;
                float vu = t1[r][i + c];
                q10 += vu * wa; q11 += vu * wb;
            }
        G00[i]=s00; G01[i]=s01; G10[i]=s10; G11[i]=s11; U10[i]=q10; U11[i]=q11;
    }
    #pragma unroll
    for (int r = 0; r < 3; r++)
        #pragma unroll
        for (int c = 0; c < 3; c++) {
            float va = t0[r][c];
            L00 += va * w0[r*3+c]; L01 += va * w1[r*3+c];
        }

    // p_{t} recompute at own / left / up
    float4 P0 = ldg4(pin + pix);
    float4 P1 = ldg4(pin + HW + pix);
    float4 P2 = ldg4(pin + 2*HW + pix);
    float4 P3 = ldg4(pin + 3*HW + pix);
    const float* p0 = &P0.x; const float* p1 = &P1.x;
    const float* p2 = &P2.x; const float* p3 = &P3.x;

    bool hasU = (y > 0);
    float4 PU2 = hasU ? ldg4(pin + 2*HW + pix - WW) : make_float4(0.f,0.f,0.f,0.f);
    float4 PU3 = hasU ? ldg4(pin + 3*HW + pix - WW) : make_float4(0.f,0.f,0.f,0.f);
    const float* pu2 = &PU2.x; const float* pu3 = &PU3.x;

    bool hasL = (x0 > 0);
    float pl0 = hasL ? pin[pix - 1]      : 0.f;
    float pl1 = hasL ? pin[HW + pix - 1] : 0.f;

    float np0[4], np1[4], np2[4], np3[4];
    #pragma unroll
    for (int i = 0; i < 4; i++) {
        np0[i] = (p0[i] + rr * G00[i]) * inv;
        np1[i] = (p1[i] + rr * G01[i]) * inv;
        np2[i] = (p2[i] + rr * G10[i]) * inv;
        np3[i] = (p3[i] + rr * G11[i]) * inv;
    }
    float lft0 = hasL ? (pl0 + rr * L00) * inv : 0.f;
    float lft1 = hasL ? (pl1 + rr * L01) * inv : 0.f;

    float wx0 = __ldg(&wx[0]), wx1v = __ldg(&wx[1]);
    float wy0 = __ldg(&wy[0]), wy1v = __ldg(&wy[1]);

    float o0[4], o1[4];
    #pragma unroll
    for (int i = 0; i < 4; i++) {
        float pL0 = (i == 0) ? lft0 : np0[i-1];
        float pL1 = (i == 0) ? lft1 : np1[i-1];
        float pU2 = hasU ? (pu2[i] + rr * U10[i]) * inv : 0.f;
        float pU3 = hasU ? (pu3[i] + rr * U11[i]) * inv : 0.f;
        float d0 = pL0 * wx0 + np0[i] * wx1v + pU2 * wy0 + np2[i] * wy1v;
        float d1 = pL1 * wx0 + np1[i] * wx1v + pU3 * wy0 + np3[i] * wy1v;
        o0[i] = v0[i] + theta * d0;
        o1[i] = v1[i] + theta * d1;
    }

    *(float4*)(uout + pix)      = make_float4(o0[0],o0[1],o0[2],o0[3]);
    *(float4*)(uout + HW + pix) = make_float4(o1[0],o1[1],o1[2],o1[3]);

    if (MODE == 1) {
        *(float4*)(pout + pix)        = make_float4(np0[0],np0[1],np0[2],np0[3]);
        *(float4*)(pout + HW + pix)   = make_float4(np1[0],np1[1],np1[2],np1[3]);
        *(float4*)(pout + 2*HW + pix) = make_float4(np2[0],np2[1],np2[2],np2[3]);
        *(float4*)(pout + 3*HW + pix) = make_float4(np3[0],np3[1],np3[2],np3[3]);
    }
}

// ---------------- launch ----------------
extern "C" void kernel_launch(void* const* d_in, const int* in_sizes, int n_in,
                              void* d_out, int out_size) {
    const float* x   = (const float*)d_in[0];
    const float* gw  = (const float*)d_in[1];
    const float* wx  = (const float*)d_in[2];
    const float* wy  = (const float*)d_in[3];
    const float* lam = (const float*)d_in[4];
    const float* tau = (const float*)d_in[5];
    const float* th  = (const float*)d_in[6];
    float* out = (float*)d_out;

    float* ubase; cudaGetSymbolAddress((void**)&ubase, g_u);
    float* pbase; cudaGetSymbolAddress((void**)&pbase, g_p);
    float* ubuf[2] = { ubase, ubase + 2*HW };
    float* pbuf[2] = { pbase, pbase + 4*HW };

    k_init<<<NB4, NT>>>(x, gw);

    k_fused<0><<<NB4, NT>>>(nullptr, ubuf[1], nullptr, nullptr, gw, wx, wy, lam, tau, th);

    for (int t = 1; t <= 9; t++) {
        k_reduce<<<NB4, NT>>>(ubuf[t & 1], gw);
        float* uo = (t == 9) ? out : ubuf[(t + 1) & 1];
        if (t < 9)
            k_fused<1><<<NB4, NT>>>(ubuf[t & 1], uo, pbuf[(t + 1) & 1], pbuf[t & 1],
                                    gw, wx, wy, lam, tau, th);
        else
            k_fused<2><<<NB4, NT>>>(ubuf[t & 1], uo, pbuf[(t + 1) & 1], nullptr,
                                    gw, wx, wy, lam, tau, th);
    }
}